// round 2
// baseline (speedup 1.0000x reference)
#include <cuda_runtime.h>
#include <mma.h>
#include <cstdint>

using namespace nvcuda;

#define NN    50000
#define EE    800000
#define HH    64
#define RR    8
#define LL    3
#define NPAD  50048          // 391 * 128
#define LNEPS 1e-5f
#define NEGSL 0.2f
#define LDS   68             // padded smem leading dim (68*4B = 272B, 16B multiple)

// ---------------- device scratch (no allocations allowed) ----------------
__device__ float    g_h[NPAD * HH];                       // 12.8 MB (pad rows stay 0)
__device__ float    g_pre[NPAD * RR * HH];                // 102.5 MB
__device__ float    g_ssrc[NN * RR];
__device__ float    g_sdst[NN * RR];
__device__ float    g_score[EE];                          // score -> ex -> att (reused)
__device__ unsigned g_relmax[RR];
__device__ float    g_denom[RR];

// monotone float<->uint encoding for atomicMax on floats
__device__ __forceinline__ unsigned enc_f(float f) {
    unsigned u = __float_as_uint(f);
    return (u & 0x80000000u) ? ~u : (u | 0x80000000u);
}
__device__ __forceinline__ float dec_f(unsigned u) {
    return __uint_as_float((u & 0x80000000u) ? (u ^ 0x80000000u) : ~u);
}

// ---------------- h = relu(x @ W_in^T + b_in) ----------------
__global__ void k_in(const float* __restrict__ x, const float* __restrict__ W,
                     const float* __restrict__ b) {
    __shared__ float Ws[64][65];
    int tid = threadIdx.x;
    for (int i = tid; i < 64 * 64; i += 256) Ws[i >> 6][i & 63] = W[i];
    __syncthreads();
    int node = blockIdx.x * 4 + (tid >> 6);
    int k    = tid & 63;
    if (node >= NN) return;
    const float* xr = x + node * 64;
    float acc = b[k];
#pragma unroll
    for (int j = 0; j < 64; j++) acc += xr[j] * Ws[k][j];
    g_h[node * 64 + k] = fmaxf(acc, 0.f);
}

// ---------------- out = h @ W_out^T + b_out ----------------
__global__ void k_out(const float* __restrict__ W, const float* __restrict__ b,
                      float* __restrict__ out) {
    __shared__ float Ws[64][65];
    int tid = threadIdx.x;
    for (int i = tid; i < 64 * 64; i += 256) Ws[i >> 6][i & 63] = W[i];
    __syncthreads();
    int node = blockIdx.x * 4 + (tid >> 6);
    int k    = tid & 63;
    if (node >= NN) return;
    const float* hr = g_h + node * 64;
    float acc = b[k];
#pragma unroll
    for (int j = 0; j < 64; j++) acc += hr[j] * Ws[k][j];
    out[node * 64 + k] = acc;
}

// ---------------- per-node attention pre-scores + stat reset ----------------
__global__ void k_scores(const float* __restrict__ Watt) {
    int idx = blockIdx.x * 256 + threadIdx.x;          // grid covers N*R*2 exactly
    if (idx < RR) { g_relmax[idx] = 0u; g_denom[idx] = 0.f; }
    int which = idx & 1;
    int r     = (idx >> 1) & 7;
    int n     = idx >> 4;
    const float* hr = g_h + n * 64;
    const float* w  = Watt + r * 128 + which * 64;
    float s = 0.f;
#pragma unroll
    for (int j = 0; j < 64; j++) s += hr[j] * w[j];
    if (which == 0) g_ssrc[n * RR + r] = s;
    else            g_sdst[n * RR + r] = s;
}

// ---------------- edge scores + per-relation max ----------------
__global__ void k_edge1(const int* __restrict__ src, const int* __restrict__ dst,
                        const int* __restrict__ et, const float* __restrict__ batt) {
    __shared__ unsigned smax[RR];
    if (threadIdx.x < RR) smax[threadIdx.x] = 0u;
    __syncthreads();
    int e = blockIdx.x * 256 + threadIdx.x;
    if (e < EE) {
        int t = et[e];
        float sc = g_ssrc[src[e] * RR + t] + g_sdst[dst[e] * RR + t] + __ldg(&batt[t]);
        sc = sc >= 0.f ? sc : NEGSL * sc;               // leaky relu
        g_score[e] = sc;
        atomicMax(&smax[t], enc_f(sc));
    }
    __syncthreads();
    if (threadIdx.x < RR) atomicMax(&g_relmax[threadIdx.x], smax[threadIdx.x]);
}

// ---------------- exp(score - max) + per-relation denom ----------------
__global__ void k_edge2(const int* __restrict__ et) {
    __shared__ float ssum[RR];
    if (threadIdx.x < RR) ssum[threadIdx.x] = 0.f;
    __syncthreads();
    int e = blockIdx.x * 256 + threadIdx.x;
    if (e < EE) {
        int t = et[e];
        float m  = dec_f(g_relmax[t]);
        float ex = __expf(g_score[e] - m);
        g_score[e] = ex;
        atomicAdd(&ssum[t], ex);
    }
    __syncthreads();
    if (threadIdx.x < RR) atomicAdd(&g_denom[threadIdx.x], ssum[threadIdx.x]);
}

// ---------------- att = ex / denom (once per edge, keeps MUFU out of scatter) --
__global__ void k_att(const int* __restrict__ et) {
    int e = blockIdx.x * 256 + threadIdx.x;
    if (e < EE) g_score[e] = g_score[e] / g_denom[et[e]];
}

// ---------------- zero the scatter target ----------------
__global__ void k_zero() {
    size_t i = ((size_t)blockIdx.x * 256 + threadIdx.x) * 4;   // grid covers exactly
    *(float4*)(g_pre + i) = make_float4(0.f, 0.f, 0.f, 0.f);
}

// ---------------- pre[dst,t] += att * h[src]  (16 threads/edge, v4 red) -------
__global__ void k_scatter(const int* __restrict__ src, const int* __restrict__ dst,
                          const int* __restrict__ et) {
    int gid = blockIdx.x * 256 + threadIdx.x;
    int e = gid >> 4;
    int q = gid & 15;
    if (e >= EE) return;
    int s = src[e], d = dst[e], t = et[e];
    float att = g_score[e];
    float4 hv = *(const float4*)(g_h + s * 64 + q * 4);
    float* p = g_pre + ((size_t)d * RR + t) * HH + q * 4;
    asm volatile("red.global.add.v4.f32 [%0], {%1,%2,%3,%4};"
                 :: "l"(p), "f"(hv.x * att), "f"(hv.y * att),
                    "f"(hv.z * att), "f"(hv.w * att) : "memory");
}

// ---------------- combine: agg GEMM + gate GEMM + mean_r + LN + relu ----------
// block = 128 nodes, 8 warps. wmma tf32 m16n16k8, fp32 accumulate.
// agg[n,r,k]  = sum_h pre[n,r,h] * W_rel[r][k][h]   (B col-major, ldb=64)
// gate[n,r,k] = sigmoid(sum_h h[n,h] * W_gate[r][k][h] + b_gate[r,k])
// h_new = mean_r gate*agg ; h = relu(LN(h + h_new))
__global__ void __launch_bounds__(256) k_combine(
    const float* __restrict__ Wrel, const float* __restrict__ Wgate,
    const float* __restrict__ bgate, const float* __restrict__ gamma,
    const float* __restrict__ beta) {
    __shared__ float s_buf[128 * LDS];   // per-warp gate scratch during r-loop; gsum at end

    int tid  = threadIdx.x;
    int w    = tid >> 5;
    int lane = tid & 31;
    int node0 = blockIdx.x * 128;
    int nw    = node0 + w * 16;

    using FA = wmma::fragment<wmma::matrix_a, 16, 16, 8, wmma::precision::tf32, wmma::row_major>;
    using FB = wmma::fragment<wmma::matrix_b, 16, 16, 8, wmma::precision::tf32, wmma::col_major>;
    using FC = wmma::fragment<wmma::accumulator, 16, 16, 8, float>;

    FC gsum[4];
#pragma unroll
    for (int j = 0; j < 4; j++) wmma::fill_fragment(gsum[j], 0.f);

    float* scw = s_buf + (size_t)w * 16 * LDS;

    for (int r = 0; r < RR; r++) {
        FC agg[4], gate[4];
#pragma unroll
        for (int j = 0; j < 4; j++) { wmma::fill_fragment(agg[j], 0.f); wmma::fill_fragment(gate[j], 0.f); }
        const float* preA = g_pre + ((size_t)nw * RR + r) * HH;
        const float* hA   = g_h + (size_t)nw * HH;
        const float* Br   = Wrel  + r * 4096;
        const float* Bg   = Wgate + r * 4096;
#pragma unroll
        for (int kk = 0; kk < 8; kk++) {
            FA apre, ah;
            wmma::load_matrix_sync(apre, preA + kk * 8, RR * HH);
            wmma::load_matrix_sync(ah,   hA   + kk * 8, HH);
#pragma unroll
            for (int i = 0; i < apre.num_elements; i++) {
                apre.x[i] = wmma::__float_to_tf32(apre.x[i]);
                ah.x[i]   = wmma::__float_to_tf32(ah.x[i]);
            }
#pragma unroll
            for (int j = 0; j < 4; j++) {
                FB br, bg;
                wmma::load_matrix_sync(br, Br + j * 16 * HH + kk * 8, HH);
                wmma::load_matrix_sync(bg, Bg + j * 16 * HH + kk * 8, HH);
#pragma unroll
                for (int i = 0; i < br.num_elements; i++) {
                    br.x[i] = wmma::__float_to_tf32(br.x[i]);
                    bg.x[i] = wmma::__float_to_tf32(bg.x[i]);
                }
                wmma::mma_sync(agg[j],  apre, br, agg[j]);
                wmma::mma_sync(gate[j], ah,   bg, gate[j]);
            }
        }
        // gate: smem round-trip for +bias / sigmoid (col index known in smem)
#pragma unroll
        for (int j = 0; j < 4; j++)
            wmma::store_matrix_sync(scw + j * 16, gate[j], LDS, wmma::mem_row_major);
        __syncwarp();
#pragma unroll 4
        for (int i2 = lane; i2 < 16 * 64; i2 += 32) {
            int rr = i2 >> 6, cc = i2 & 63;
            float gv = scw[rr * LDS + cc] + __ldg(&bgate[r * HH + cc]);
            scw[rr * LDS + cc] = 1.f / (1.f + __expf(-gv));
        }
        __syncwarp();
#pragma unroll
        for (int j = 0; j < 4; j++) {
            FC gt;
            wmma::load_matrix_sync(gt, scw + j * 16, LDS, wmma::mem_row_major);
#pragma unroll
            for (int i = 0; i < 8; i++) gsum[j].x[i] += gt.x[i] * agg[j].x[i];
        }
        __syncwarp();
    }
    // park gsum in smem (reuses the scratch region: r-loop is done)
#pragma unroll
    for (int j = 0; j < 4; j++)
        wmma::store_matrix_sync(s_buf + (size_t)(w * 16) * LDS + j * 16, gsum[j], LDS,
                                wmma::mem_row_major);
    __syncthreads();

    // epilogue: 2 threads per node (each 32 cols), LN + relu, write h in place
    int ni   = tid >> 1;
    int half = tid & 1;
    int n    = node0 + ni;
    const float* hr = g_h + (size_t)n * HH + half * 32;
    const float* gs = s_buf + (size_t)ni * LDS + half * 32;
    float v[32];
    float ssum = 0.f, ssq = 0.f;
#pragma unroll
    for (int c = 0; c < 32; c++) {
        float val = hr[c] + gs[c] * (1.f / RR);
        v[c] = val; ssum += val; ssq += val * val;
    }
    ssum += __shfl_xor_sync(0xffffffffu, ssum, 1);
    ssq  += __shfl_xor_sync(0xffffffffu, ssq, 1);
    float mu   = ssum * (1.f / 64.f);
    float var  = ssq * (1.f / 64.f) - mu * mu;
    float rstd = rsqrtf(var + LNEPS);
    float* ho = g_h + (size_t)n * HH + half * 32;
#pragma unroll
    for (int c = 0; c < 32; c++) {
        int col = half * 32 + c;
        float y = (v[c] - mu) * rstd * __ldg(&gamma[col]) + __ldg(&beta[col]);
        ho[c] = fmaxf(y, 0.f);
    }
}

// ---------------- launch ----------------
extern "C" void kernel_launch(void* const* d_in, const int* in_sizes, int n_in,
                              void* d_out, int out_size) {
    const float* x      = (const float*)d_in[0];
    const int*   ei     = (const int*)d_in[1];
    const int*   src    = ei;
    const int*   dst    = ei + EE;
    const int*   et     = (const int*)d_in[2];
    const float* W_in   = (const float*)d_in[3];
    const float* b_in   = (const float*)d_in[4];
    const float* W_rel  = (const float*)d_in[5];
    const float* W_gate = (const float*)d_in[6];
    const float* b_gate = (const float*)d_in[7];
    const float* W_att  = (const float*)d_in[8];
    const float* b_att  = (const float*)d_in[9];
    const float* ln_g   = (const float*)d_in[10];
    const float* ln_b   = (const float*)d_in[11];
    const float* W_out  = (const float*)d_in[12];
    const float* b_out  = (const float*)d_in[13];

    k_in<<<12500, 256>>>(x, W_in, b_in);
    for (int l = 0; l < LL; l++) {
        k_scores<<<3125, 256>>>(W_att);                       // + resets relmax/denom
        k_edge1<<<3125, 256>>>(src, dst, et, b_att);
        k_edge2<<<3125, 256>>>(et);
        k_att<<<3125, 256>>>(et);
        k_zero<<<25024, 256>>>();
        k_scatter<<<50000, 256>>>(src, dst, et);
        k_combine<<<391, 256>>>(W_rel, W_gate, b_gate, ln_g + l * HH, ln_b + l * HH);
    }
    k_out<<<12500, 256>>>(W_out, b_out, (float*)d_out);
}

// round 4
// speedup vs baseline: 1.0354x; 1.0354x over previous
#include <cuda_runtime.h>
#include <mma.h>
#include <cstdint>

using namespace nvcuda;

#define NN    50000
#define EE    800000
#define HH    64
#define RR    8
#define LL    3
#define NPAD  50048          // 391 * 128
#define NR    (NN * RR)      // 400000 segments
#define LNEPS 1e-5f
#define NEGSL 0.2f
#define LDS   68             // padded smem leading dim (68*4B = 272B, 16B multiple)

// ---------------- device scratch (no allocations allowed) ----------------
__device__ float    g_h[NPAD * HH];                       // 12.8 MB (pad rows stay 0)
__device__ float    g_ssrc[NN * RR];
__device__ float    g_sdst[NN * RR];
__device__ float    g_score[EE];                          // score -> ex (reused)
__device__ unsigned g_relmax[RR];
__device__ float    g_denom[RR];
// CSR (built once per launch; edge structure is layer-invariant)
__device__ int      g_cnt[NR];                            // histogram
__device__ int      g_off[NR + 1];                        // exclusive offsets
__device__ int      g_cur[NR];                            // scatter cursors
__device__ int      g_bsum[512];                          // per-block scan sums
__device__ int      g_srcs[EE];                           // src, segment-sorted
__device__ int      g_eord[EE];                           // original edge id, sorted
__device__ float    g_atts[EE];                           // att, segment-sorted

// monotone float<->uint encoding for atomicMax on floats
__device__ __forceinline__ unsigned enc_f(float f) {
    unsigned u = __float_as_uint(f);
    return (u & 0x80000000u) ? ~u : (u | 0x80000000u);
}
__device__ __forceinline__ float dec_f(unsigned u) {
    return __uint_as_float((u & 0x80000000u) ? (u ^ 0x80000000u) : ~u);
}

// ---------------- h = relu(x @ W_in^T + b_in) ----------------
__global__ void k_in(const float* __restrict__ x, const float* __restrict__ W,
                     const float* __restrict__ b) {
    __shared__ float Ws[64][65];
    int tid = threadIdx.x;
    for (int i = tid; i < 64 * 64; i += 256) Ws[i >> 6][i & 63] = W[i];
    __syncthreads();
    int node = blockIdx.x * 4 + (tid >> 6);
    int k    = tid & 63;
    if (node >= NN) return;
    const float* xr = x + node * 64;
    float acc = b[k];
#pragma unroll
    for (int j = 0; j < 64; j++) acc += xr[j] * Ws[k][j];
    g_h[node * 64 + k] = fmaxf(acc, 0.f);
}

// ---------------- out = h @ W_out^T + b_out ----------------
__global__ void k_out(const float* __restrict__ W, const float* __restrict__ b,
                      float* __restrict__ out) {
    __shared__ float Ws[64][65];
    int tid = threadIdx.x;
    for (int i = tid; i < 64 * 64; i += 256) Ws[i >> 6][i & 63] = W[i];
    __syncthreads();
    int node = blockIdx.x * 4 + (tid >> 6);
    int k    = tid & 63;
    if (node >= NN) return;
    const float* hr = g_h + node * 64;
    float acc = b[k];
#pragma unroll
    for (int j = 0; j < 64; j++) acc += hr[j] * Ws[k][j];
    out[node * 64 + k] = acc;
}

// =================== CSR build (once per launch) ===================
__global__ void k_cnt_zero() {
    int i = blockIdx.x * 256 + threadIdx.x;
    if (i < NR) g_cnt[i] = 0;
}
__global__ void k_hist(const int* __restrict__ dst, const int* __restrict__ et) {
    int e = blockIdx.x * 256 + threadIdx.x;
    if (e < EE) atomicAdd(&g_cnt[dst[e] * RR + et[e]], 1);
}
// block scans 1024 elements (256 threads x 4); writes per-element exclusive
// (within block) and block total to g_bsum
__global__ void k_scan1() {
    __shared__ int s[256];
    int t = threadIdx.x;
    int base = blockIdx.x * 1024 + t * 4;
    int v0 = base + 0 < NR ? g_cnt[base + 0] : 0;
    int v1 = base + 1 < NR ? g_cnt[base + 1] : 0;
    int v2 = base + 2 < NR ? g_cnt[base + 2] : 0;
    int v3 = base + 3 < NR ? g_cnt[base + 3] : 0;
    int tsum = v0 + v1 + v2 + v3;
    s[t] = tsum;
    __syncthreads();
#pragma unroll
    for (int off = 1; off < 256; off <<= 1) {
        int add = (t >= off) ? s[t - off] : 0;
        __syncthreads();
        s[t] += add;
        __syncthreads();
    }
    int exc = s[t] - tsum;                       // exclusive prefix of this thread
    if (base + 0 < NR) g_off[base + 0] = exc;
    if (base + 1 < NR) g_off[base + 1] = exc + v0;
    if (base + 2 < NR) g_off[base + 2] = exc + v0 + v1;
    if (base + 3 < NR) g_off[base + 3] = exc + v0 + v1 + v2;
    if (t == 255) g_bsum[blockIdx.x] = s[255];
}
__global__ void k_scan2(int nblocks) {
    __shared__ int s[512];
    int t = threadIdx.x;
    int v = (t < nblocks) ? g_bsum[t] : 0;
    s[t] = v;
    __syncthreads();
#pragma unroll
    for (int off = 1; off < 512; off <<= 1) {
        int add = (t >= off) ? s[t - off] : 0;
        __syncthreads();
        s[t] += add;
        __syncthreads();
    }
    if (t < nblocks) g_bsum[t] = s[t] - v;       // exclusive
    if (t == 0) g_off[NR] = EE;
}
__global__ void k_scan3() {
    int i = blockIdx.x * 256 + threadIdx.x;
    if (i < NR) {
        int v = g_off[i] + g_bsum[i >> 10];
        g_off[i] = v;
        g_cur[i] = v;
    }
}
__global__ void k_csr(const int* __restrict__ src, const int* __restrict__ dst,
                      const int* __restrict__ et) {
    int e = blockIdx.x * 256 + threadIdx.x;
    if (e >= EE) return;
    int seg = dst[e] * RR + et[e];
    int p = atomicAdd(&g_cur[seg], 1);
    g_srcs[p] = src[e];
    g_eord[p] = e;
}

// =================== per-layer edge pipeline ===================
__global__ void k_scores(const float* __restrict__ Watt) {
    int idx = blockIdx.x * 256 + threadIdx.x;          // grid covers N*R*2 exactly
    if (idx < RR) { g_relmax[idx] = 0u; g_denom[idx] = 0.f; }
    int which = idx & 1;
    int r     = (idx >> 1) & 7;
    int n     = idx >> 4;
    const float* hr = g_h + n * 64;
    const float* w  = Watt + r * 128 + which * 64;
    float s = 0.f;
#pragma unroll
    for (int j = 0; j < 64; j++) s += hr[j] * w[j];
    if (which == 0) g_ssrc[n * RR + r] = s;
    else            g_sdst[n * RR + r] = s;
}

__global__ void k_edge1(const int* __restrict__ src, const int* __restrict__ dst,
                        const int* __restrict__ et, const float* __restrict__ batt) {
    __shared__ unsigned smax[RR];
    if (threadIdx.x < RR) smax[threadIdx.x] = 0u;
    __syncthreads();
    int e = blockIdx.x * 256 + threadIdx.x;
    if (e < EE) {
        int t = et[e];
        float sc = g_ssrc[src[e] * RR + t] + g_sdst[dst[e] * RR + t] + __ldg(&batt[t]);
        sc = sc >= 0.f ? sc : NEGSL * sc;               // leaky relu
        g_score[e] = sc;
        atomicMax(&smax[t], enc_f(sc));
    }
    __syncthreads();
    if (threadIdx.x < RR) atomicMax(&g_relmax[threadIdx.x], smax[threadIdx.x]);
}

__global__ void k_edge2(const int* __restrict__ et) {
    __shared__ float ssum[RR];
    if (threadIdx.x < RR) ssum[threadIdx.x] = 0.f;
    __syncthreads();
    int e = blockIdx.x * 256 + threadIdx.x;
    if (e < EE) {
        int t = et[e];
        float m  = dec_f(g_relmax[t]);
        float ex = __expf(g_score[e] - m);
        g_score[e] = ex;
        atomicAdd(&ssum[t], ex);
    }
    __syncthreads();
    if (threadIdx.x < RR) atomicAdd(&g_denom[threadIdx.x], ssum[threadIdx.x]);
}

// att written directly into CSR-sorted order
__global__ void k_att(const int* __restrict__ et) {
    int i = blockIdx.x * 256 + threadIdx.x;
    if (i >= EE) return;
    int e = g_eord[i];
    g_atts[i] = g_score[e] / g_denom[et[e]];
}

// =================== combine: gather + dual GEMM + LN, warp-independent ========
// block = 128 nodes, 8 warps, each warp fully owns its 16 nodes (no syncthreads).
// per r: build pre tile rows in smem via CSR gather of att*h[src], then
//   agg  = pre @ W_rel[r]^T  (wmma tf32)
//   gate = sigmoid(h @ W_gate[r]^T + b_gate[r])
//   gsum += gate * agg
// epilogue: h = relu(LN(h + gsum/R))
__global__ void __launch_bounds__(256) k_combine(
    const float* __restrict__ Wrel, const float* __restrict__ Wgate,
    const float* __restrict__ bgate, const float* __restrict__ gamma,
    const float* __restrict__ beta) {
    __shared__ float s_buf[128 * LDS];   // per-warp: pre tile -> gate scratch -> gsum

    int tid  = threadIdx.x;
    int w    = tid >> 5;
    int lane = tid & 31;
    int node0 = blockIdx.x * 128;
    int nw    = node0 + w * 16;
    int ni    = tid >> 1;                // row 0..127 (within warp's 16 rows)
    int half  = tid & 1;                 // col half: 32 floats each

    using FA = wmma::fragment<wmma::matrix_a, 16, 16, 8, wmma::precision::tf32, wmma::row_major>;
    using FB = wmma::fragment<wmma::matrix_b, 16, 16, 8, wmma::precision::tf32, wmma::col_major>;
    using FC = wmma::fragment<wmma::accumulator, 16, 16, 8, float>;

    FC gsum[4];
#pragma unroll
    for (int j = 0; j < 4; j++) wmma::fill_fragment(gsum[j], 0.f);

    float* warp_rows = s_buf + (size_t)w * 16 * LDS;
    int    node      = node0 + ni;

    for (int r = 0; r < RR; r++) {
        // ---- build pre tile rows (gather from L2-resident h) ----
        float4 acc[8];
#pragma unroll
        for (int j = 0; j < 8; j++) acc[j] = make_float4(0.f, 0.f, 0.f, 0.f);
        if (node < NN) {
            int seg   = node * RR + r;
            int start = g_off[seg];
            int end   = g_off[seg + 1];
            for (int i = start; i < end; i++) {
                int   s = g_srcs[i];
                float a = g_atts[i];
                const float4* hp = (const float4*)(g_h + (size_t)s * 64 + half * 32);
#pragma unroll
                for (int j = 0; j < 8; j++) {
                    float4 v = hp[j];
                    acc[j].x = fmaf(a, v.x, acc[j].x);
                    acc[j].y = fmaf(a, v.y, acc[j].y);
                    acc[j].z = fmaf(a, v.z, acc[j].z);
                    acc[j].w = fmaf(a, v.w, acc[j].w);
                }
            }
        }
        float* trow = s_buf + (size_t)ni * LDS + half * 32;
#pragma unroll
        for (int j = 0; j < 8; j++) *(float4*)(trow + j * 4) = acc[j];
        __syncwarp();

        // ---- dual GEMM ----
        FC agg[4], gate[4];
#pragma unroll
        for (int j = 0; j < 4; j++) { wmma::fill_fragment(agg[j], 0.f); wmma::fill_fragment(gate[j], 0.f); }
        const float* hA = g_h + (size_t)nw * HH;
        const float* Br = Wrel  + r * 4096;
        const float* Bg = Wgate + r * 4096;
#pragma unroll
        for (int kk = 0; kk < 8; kk++) {
            FA apre, ah;
            wmma::load_matrix_sync(apre, warp_rows + kk * 8, LDS);
            wmma::load_matrix_sync(ah,   hA + kk * 8, HH);
#pragma unroll
            for (int i = 0; i < apre.num_elements; i++) {
                apre.x[i] = wmma::__float_to_tf32(apre.x[i]);
                ah.x[i]   = wmma::__float_to_tf32(ah.x[i]);
            }
#pragma unroll
            for (int j = 0; j < 4; j++) {
                FB br, bg;
                wmma::load_matrix_sync(br, Br + j * 16 * HH + kk * 8, HH);
                wmma::load_matrix_sync(bg, Bg + j * 16 * HH + kk * 8, HH);
#pragma unroll
                for (int i = 0; i < br.num_elements; i++) {
                    br.x[i] = wmma::__float_to_tf32(br.x[i]);
                    bg.x[i] = wmma::__float_to_tf32(bg.x[i]);
                }
                wmma::mma_sync(agg[j],  apre, br, agg[j]);
                wmma::mma_sync(gate[j], ah,   bg, gate[j]);
            }
        }
        // ---- gate: +bias, sigmoid via warp-private smem scratch (reuses tile) ----
#pragma unroll
        for (int j = 0; j < 4; j++)
            wmma::store_matrix_sync(warp_rows + j * 16, gate[j], LDS, wmma::mem_row_major);
        __syncwarp();
#pragma unroll 4
        for (int i2 = lane; i2 < 16 * 64; i2 += 32) {
            int rr = i2 >> 6, cc = i2 & 63;
            float gv = warp_rows[rr * LDS + cc] + __ldg(&bgate[r * HH + cc]);
            warp_rows[rr * LDS + cc] = 1.f / (1.f + __expf(-gv));
        }
        __syncwarp();
#pragma unroll
        for (int j = 0; j < 4; j++) {
            FC gt;
            wmma::load_matrix_sync(gt, warp_rows + j * 16, LDS, wmma::mem_row_major);
#pragma unroll
            for (int i = 0; i < 8; i++) gsum[j].x[i] += gt.x[i] * agg[j].x[i];
        }
        __syncwarp();
    }
    // ---- park gsum in warp's rows, then LN epilogue (still warp-local) ----
#pragma unroll
    for (int j = 0; j < 4; j++)
        wmma::store_matrix_sync(warp_rows + j * 16, gsum[j], LDS, wmma::mem_row_major);
    __syncwarp();

    const float* hr = g_h + (size_t)node * HH + half * 32;
    const float* gs = s_buf + (size_t)ni * LDS + half * 32;
    float v[32];
    float ssum = 0.f, ssq = 0.f;
#pragma unroll
    for (int c = 0; c < 32; c++) {
        float val = hr[c] + gs[c] * (1.f / RR);
        v[c] = val; ssum += val; ssq += val * val;
    }
    ssum += __shfl_xor_sync(0xffffffffu, ssum, 1);
    ssq  += __shfl_xor_sync(0xffffffffu, ssq, 1);
    float mu   = ssum * (1.f / 64.f);
    float var  = ssq * (1.f / 64.f) - mu * mu;
    float rstd = rsqrtf(var + LNEPS);
    float* ho = g_h + (size_t)node * HH + half * 32;
#pragma unroll
    for (int c = 0; c < 32; c++) {
        int col = half * 32 + c;
        float y = (v[c] - mu) * rstd * __ldg(&gamma[col]) + __ldg(&beta[col]);
        ho[c] = fmaxf(y, 0.f);
    }
}

// ---------------- launch ----------------
extern "C" void kernel_launch(void* const* d_in, const int* in_sizes, int n_in,
                              void* d_out, int out_size) {
    const float* x      = (const float*)d_in[0];
    const int*   ei     = (const int*)d_in[1];
    const int*   src    = ei;
    const int*   dst    = ei + EE;
    const int*   et     = (const int*)d_in[2];
    const float* W_in   = (const float*)d_in[3];
    const float* b_in   = (const float*)d_in[4];
    const float* W_rel  = (const float*)d_in[5];
    const float* W_gate = (const float*)d_in[6];
    const float* b_gate = (const float*)d_in[7];
    const float* W_att  = (const float*)d_in[8];
    const float* b_att  = (const float*)d_in[9];
    const float* ln_g   = (const float*)d_in[10];
    const float* ln_b   = (const float*)d_in[11];
    const float* W_out  = (const float*)d_in[12];
    const float* b_out  = (const float*)d_in[13];

    k_in<<<12500, 256>>>(x, W_in, b_in);

    // CSR build (edge structure is layer-invariant)
    k_cnt_zero<<<1563, 256>>>();
    k_hist<<<3125, 256>>>(dst, et);
    k_scan1<<<391, 256>>>();
    k_scan2<<<1, 512>>>(391);
    k_scan3<<<1563, 256>>>();
    k_csr<<<3125, 256>>>(src, dst, et);

    for (int l = 0; l < LL; l++) {
        k_scores<<<3125, 256>>>(W_att);                       // + resets relmax/denom
        k_edge1<<<3125, 256>>>(src, dst, et, b_att);
        k_edge2<<<3125, 256>>>(et);
        k_att<<<3125, 256>>>(et);
        k_combine<<<391, 256>>>(W_rel, W_gate, b_gate, ln_g + l * HH, ln_b + l * HH);
    }
    k_out<<<12500, 256>>>(W_out, b_out, (float*)d_out);
}